// round 17
// baseline (speedup 1.0000x reference)
#include <cuda_runtime.h>
#include <math.h>

#define NB 256
#define S  4096
#define FO 8
#define NM 64
#define FM 6
#define EPSF 1e-5f

#define PBLK 16     // proc stats sub-blocks per instance
#define OSB  4      // opes stats sub-blocks per instance
#define NPB  32     // proc norm sub-blocks per instance
#define OPB  8      // opes norm sub-blocks per instance
#define NSTAT (PBLK + OSB)     // 20
#define NNORM (NPB + OPB)      // 40
#define LEAD  32               // proven: full L2 reuse + minimal spin
#define GRID_T (NB * (NSTAT + NNORM))   // 15360

// -------- device scratch (fixed slots; flags self-reset each replay) --------
__device__ float g_part[NB][PBLK][4];
__device__ float g_opart[NB][OSB][2][FO];
__device__ float g_mmean[NB * FM];
__device__ float g_mrstd[NB * FM];
__device__ unsigned g_cnt[NB],  g_fin[NB];
__device__ unsigned g_ocnt[NB], g_ofin[NB];

__device__ __forceinline__ float warp_sum(float v) {
#pragma unroll
    for (int o = 16; o > 0; o >>= 1) v += __shfl_down_sync(0xffffffffu, v, o);
    return v;
}

__device__ __forceinline__ void wait_for(unsigned* cnt, unsigned target) {
    if (threadIdx.x == 0) {
        volatile unsigned* p = (volatile unsigned*)cnt;
        while (*p < target) __nanosleep(32);
        __threadfence();
    }
    __syncthreads();
}

__device__ __forceinline__ void retire(unsigned* fin, unsigned* cnt, unsigned nCons) {
    if (threadIdx.x == 0) {
        unsigned o = atomicAdd(fin, 1u);
        if (o == nCons - 1) { *cnt = 0u; *fin = 0u; }
    }
}

// ---------------- role bodies ----------------
__device__ void proc_stats(const float4* __restrict__ pt, int b, int sub) {
    const float4* src = pt + (size_t)b * (S * NM / 4) + (size_t)sub * 4096;
    float s = 0.f, ss = 0.f, c = 0.f;
    for (int i0 = threadIdx.x; i0 < 4096; i0 += 1024) {
        float4 v[4];
#pragma unroll
        for (int k = 0; k < 4; k++) v[k] = src[i0 + k * 256];   // cached: prime L2 for norm
#pragma unroll
        for (int k = 0; k < 4; k++) {
            s  += (v[k].x + v[k].y) + (v[k].z + v[k].w);
            ss += (v[k].x * v[k].x + v[k].y * v[k].y) + (v[k].z * v[k].z + v[k].w * v[k].w);
            c  += (float)((v[k].x != 0.f) + (v[k].y != 0.f) + (v[k].z != 0.f) + (v[k].w != 0.f));
        }
    }
    __shared__ float sh[3][8];
    int lane = threadIdx.x & 31, w = threadIdx.x >> 5;
    s = warp_sum(s); ss = warp_sum(ss); c = warp_sum(c);
    if (lane == 0) { sh[0][w] = s; sh[1][w] = ss; sh[2][w] = c; }
    __syncthreads();
    if (threadIdx.x == 0) {
        float ts = 0.f, tss = 0.f, tc = 0.f;
#pragma unroll
        for (int i = 0; i < 8; i++) { ts += sh[0][i]; tss += sh[1][i]; tc += sh[2][i]; }
        g_part[b][sub][0] = ts;
        g_part[b][sub][1] = tss;
        g_part[b][sub][2] = tc;
        __threadfence();
        atomicAdd(&g_cnt[b], 1u);
    }
}

__device__ void opes_stats(const float* __restrict__ opes, const float* __restrict__ mas,
                           const int* __restrict__ nums, int b, int sub) {
    const int n  = nums[b];
    const int r0 = sub * 1024;
    const int r1 = min(r0 + 1024, n);

    float s[FO], q[FO];
#pragma unroll
    for (int f = 0; f < FO; f++) { s[f] = 0.f; q[f] = 0.f; }

    const float4* op = (const float4*)(opes + (size_t)b * S * FO);
    for (int r = r0 + threadIdx.x; r < r1; r += 256) {
        float4 a  = op[r * 2];          // cached: prime L2 for norm
        float4 b4 = op[r * 2 + 1];
        float x[FO] = {a.x, a.y, a.z, a.w, b4.x, b4.y, b4.z, b4.w};
#pragma unroll
        for (int f = 0; f < FO; f++) { s[f] += x[f]; q[f] += x[f] * x[f]; }
    }
    __shared__ float sh[16][8];
    int lane = threadIdx.x & 31, w = threadIdx.x >> 5;
#pragma unroll
    for (int f = 0; f < FO; f++) {
        float rs = warp_sum(s[f]);
        float rq = warp_sum(q[f]);
        if (lane == 0) { sh[f][w] = rs; sh[f + 8][w] = rq; }
    }
    __syncthreads();
    if (threadIdx.x < FO) {
        int f = threadIdx.x;
        float ts = 0.f, tq = 0.f;
#pragma unroll
        for (int i = 0; i < 8; i++) { ts += sh[f][i]; tq += sh[f + 8][i]; }
        g_opart[b][sub][0][f] = ts;
        g_opart[b][sub][1][f] = tq;
    }
    if (sub == 0 && threadIdx.x >= 64 && threadIdx.x < 64 + FM) {
        int f = threadIdx.x - 64;
        const float* mp = mas + (size_t)b * NM * FM + f;
        float ts = 0.f, tq = 0.f;
#pragma unroll
        for (int m = 0; m < NM; m++) { float x = mp[m * FM]; ts += x; tq += x * x; }
        float fm   = (float)NM;
        float mean = ts / fm;
        float var  = (tq - ts * ts / fm) / (fm - 1.f);
        g_mmean[b * FM + f] = mean;
        g_mrstd[b * FM + f] = 1.f / (sqrtf(var) + EPSF);
    }
    __syncthreads();
    if (threadIdx.x == 0) { __threadfence(); atomicAdd(&g_ocnt[b], 1u); }
}

__device__ void proc_norm(const float4* __restrict__ pt, float4* __restrict__ out_proc,
                          int b, int sub) {
    wait_for(&g_cnt[b], PBLK);

    __shared__ float sm, sr;
    if (threadIdx.x < 32) {
        int lane = threadIdx.x;
        float s = 0.f, ss = 0.f, c = 0.f;
        if (lane < PBLK) {
            s  = g_part[b][lane][0];
            ss = g_part[b][lane][1];
            c  = g_part[b][lane][2];
        }
#pragma unroll
        for (int o = 8; o > 0; o >>= 1) {
            s  += __shfl_down_sync(0xffffffffu, s, o);
            ss += __shfl_down_sync(0xffffffffu, ss, o);
            c  += __shfl_down_sync(0xffffffffu, c, o);
        }
        if (lane == 0) {
            float m   = s / c;
            float var = (ss - s * s / c) / (c - 1.f);
            sm = m;
            sr = 1.f / (sqrtf(var) + EPSF);
        }
    }
    __syncthreads();
    retire(&g_fin[b], &g_cnt[b], NPB);
    const float m = sm, r = sr;

    const size_t base = (size_t)b * (S * NM / 4) + (size_t)sub * 2048;
    const float4* src = pt + base;
    float4*       dst = out_proc + base;
    // 8 loads per thread, front-batched 4-wide
    for (int i0 = threadIdx.x; i0 < 2048; i0 += 1024) {
        float4 v[4];
#pragma unroll
        for (int k = 0; k < 4; k++) v[k] = __ldcs(&src[i0 + k * 256]);
#pragma unroll
        for (int k = 0; k < 4; k++) {
            float4 o;
            o.x = (v[k].x != 0.f) ? (v[k].x - m) * r : 0.f;
            o.y = (v[k].y != 0.f) ? (v[k].y - m) * r : 0.f;
            o.z = (v[k].z != 0.f) ? (v[k].z - m) * r : 0.f;
            o.w = (v[k].w != 0.f) ? (v[k].w - m) * r : 0.f;
            __stcs(&dst[i0 + k * 256], o);
        }
    }
}

__device__ void opes_norm(const float* __restrict__ opes, float4* __restrict__ out_opes,
                          const float* __restrict__ mas, float* __restrict__ out_mas,
                          const int* __restrict__ nums, int b, int sub) {
    const int base = b * 8192 + sub * 1024;

    wait_for(&g_ocnt[b], OSB);

    __shared__ float mm[FO], rr[FO];
    if (threadIdx.x < FO) {
        const int f = threadIdx.x;
        float ts = 0.f, tq = 0.f;
#pragma unroll
        for (int s2 = 0; s2 < OSB; s2++) {
            ts += g_opart[b][s2][0][f];
            tq += g_opart[b][s2][1][f];
        }
        float fn   = (float)nums[b];
        float mean = ts / fn;
        float var  = (tq - ts * ts / fn) / (fn - 1.f);
        mm[f] = mean;
        rr[f] = 1.f / (sqrtf(var) + EPSF);
    }
    __syncthreads();
    retire(&g_ofin[b], &g_ocnt[b], OPB);

    const float4* src = (const float4*)opes;
    // 4 loads per thread, fully front-batched
    {
        const int t = threadIdx.x;
        float4 v[4];
#pragma unroll
        for (int k = 0; k < 4; k++) v[k] = __ldcs(&src[base + t + k * 256]);
        const float* M = &mm[(t & 1) * 4];
        const float* R = &rr[(t & 1) * 4];
#pragma unroll
        for (int k = 0; k < 4; k++) {
            float4 o;
            o.x = (v[k].x - M[0]) * R[0];
            o.y = (v[k].y - M[1]) * R[1];
            o.z = (v[k].z - M[2]) * R[2];
            o.w = (v[k].w - M[3]) * R[3];
            __stcs(&out_opes[base + t + k * 256], o);
        }
    }

    if (sub == 0) {
        const float* min_ = mas + (size_t)b * NM * FM;
        float*       mout = out_mas + (size_t)b * NM * FM;
        for (int i = threadIdx.x; i < NM * FM; i += 256) {
            int f = i % FM;
            mout[i] = (min_[i] - g_mmean[b * FM + f]) * g_mrstd[b * FM + f];
        }
    }
}

// ---------------- interleaved dispatch ----------------
__global__ void __launch_bounds__(256, 8)   // force 8 CTAs/SM (<=32 regs): occupancy lever
fusedAB_k(const float4* __restrict__ pt, float4* __restrict__ out_proc,
          const float* __restrict__ opes, float4* __restrict__ out_opes,
          const float* __restrict__ mas, float* __restrict__ out_mas,
          const int* __restrict__ nums) {
    const int bid = blockIdx.x;
    const int HEAD = LEAD * NSTAT;                              // 640
    const int MID  = HEAD + (NB - LEAD) * (NSTAT + NNORM);      // 14080

    int b, sub, is_stats;
    if (bid < HEAD) {
        b = bid / NSTAT; sub = bid % NSTAT; is_stats = 1;
    } else if (bid < MID) {
        int t = bid - HEAD;
        int seg = t / (NSTAT + NNORM);
        int k   = t % (NSTAT + NNORM);
        if (k < NSTAT) { b = LEAD + seg; sub = k; is_stats = 1; }
        else           { b = seg;        sub = k - NSTAT; is_stats = 0; }
    } else {
        int t = bid - MID;
        b = (NB - LEAD) + t / NNORM; sub = t % NNORM; is_stats = 0;
    }

    if (is_stats) {
        if (sub < PBLK) proc_stats(pt, b, sub);
        else            opes_stats(opes, mas, nums, b, sub - PBLK);
    } else {
        if (sub < NPB)  proc_norm(pt, out_proc, b, sub);
        else            opes_norm(opes, out_opes, mas, out_mas, nums, b, sub - NPB);
    }
}

extern "C" void kernel_launch(void* const* d_in, const int* in_sizes, int n_in,
                              void* d_out, int out_size) {
    const float* raw_opes = (const float*)d_in[0];
    const float* raw_mas  = (const float*)d_in[1];
    const float* proc     = (const float*)d_in[2];
    const int*   nums     = (const int*)d_in[3];

    float* out_opes = (float*)d_out;
    float* out_mas  = out_opes + (size_t)NB * S * FO;
    float* out_proc = out_mas  + (size_t)NB * NM * FM;

    fusedAB_k<<<GRID_T, 256>>>((const float4*)proc, (float4*)out_proc,
                               raw_opes, (float4*)out_opes,
                               raw_mas, out_mas, nums);
}